// round 1
// baseline (speedup 1.0000x reference)
#include <cuda_runtime.h>
#include <cstdint>
#include <cstdio>

// Bidirectional GRU encoder: B=64, T=512, E=512, U=1024, gates (z,r,h), reset_after=True.
// out = [B,T,2U] outputs (fwd|bwd) followed by [B,2U] final state.

#define TT   512   // seq len
#define BB   64    // batch
#define EE   512   // embedding dim
#define UU   1024  // units
#define KC   64    // K-chunk
#define NB   128   // total blocks in persistent kernel (64 per direction)
#define NPD  64    // blocks per direction
#define NTHR 128   // threads per block

typedef unsigned long long ull;

// ---------------- device scratch (static allocation only — no cudaMalloc allowed) ----
__device__ float    g_Xt[(size_t)TT * EE * BB];     // x gathered+transposed: [t][e][b], 64 MB
__device__ float    g_Ht[2][2][UU * BB];            // h state: [dir][parity][u*64+b], 2 MB
__device__ unsigned g_count;                        // global barrier counter

// ---------------- helpers ----------------
__device__ __forceinline__ ull fma2(ull a, ull b, ull c) {
    ull d;
    asm("fma.rn.f32x2 %0, %1, %2, %3;" : "=l"(d) : "l"(a), "l"(b), "l"(c));
    return d;
}
__device__ __forceinline__ float lo32(ull v) { return __uint_as_float((unsigned)v); }
__device__ __forceinline__ float hi32(ull v) { return __uint_as_float((unsigned)(v >> 32)); }

__device__ __forceinline__ void cp16(void* s, const void* g) {
    unsigned sa = (unsigned)__cvta_generic_to_shared(s);
    // .cg: bypass L1.  REQUIRED for g_Ht (cross-SM producer/consumer; L1 is not coherent).
    asm volatile("cp.async.cg.shared.global [%0], [%1], 16;" :: "r"(sa), "l"(g));
}
__device__ __forceinline__ void cp_commit() { asm volatile("cp.async.commit_group;" ::: "memory"); }
__device__ __forceinline__ void cp_wait1()  { asm volatile("cp.async.wait_group 1;" ::: "memory"); }
__device__ __forceinline__ void cp_wait0()  { asm volatile("cp.async.wait_group 0;" ::: "memory"); }

// ---------------- prep: Xt[t][e][b] = emb[enc[b][t]][e] ----------------
__global__ void prep_kernel(const int* __restrict__ enc, const float* __restrict__ emb) {
    int t = blockIdx.x;
    __shared__ int tok[BB];
    if (threadIdx.x < BB) tok[threadIdx.x] = enc[threadIdx.x * TT + t];
    __syncthreads();
    // 64 b * 128 float4 per t
    for (int i = threadIdx.x; i < BB * (EE / 4); i += blockDim.x) {
        int b  = i >> 7;       // i / 128
        int e4 = i & 127;
        float4 v = *(const float4*)(emb + (size_t)tok[b] * EE + e4 * 4);
        size_t base = ((size_t)t * EE + (size_t)e4 * 4) * BB + b;
        g_Xt[base]        = v.x;
        g_Xt[base + BB]   = v.y;
        g_Xt[base + 2*BB] = v.z;
        g_Xt[base + 3*BB] = v.w;
    }
}

// ---------------- init: h0 -> g_Ht[dir][0], reset barrier ----------------
__global__ void init_kernel(const float* __restrict__ h0f, const float* __restrict__ h0b) {
    int i = blockIdx.x * blockDim.x + threadIdx.x;  // 0 .. 131071
    if (i == 0) g_count = 0u;
    int d  = i >> 16;
    int r  = i & 65535;
    int jj = r >> 6;
    int b  = r & 63;
    const float* h0 = d ? h0b : h0f;
    g_Ht[d][0][jj * BB + b] = h0[b * UU + jj];
}

// ---------------- GEMM building blocks ----------------
// a-chunk: [KC][64] floats, contiguous 16KB from global
__device__ __forceinline__ void load_a(float* dst, const float* src) {
#pragma unroll
    for (int i = 0; i < 8; i++) {
        int idx = i * NTHR + threadIdx.x;  // float4 index, 1024 total
        cp16(dst + idx * 4, src + idx * 4);
    }
    cp_commit();
}

// w-chunk: 48 columns (3 gates x 16 j) for KC k's; gather to regs (LDG), later dup-store
__device__ __forceinline__ void ldg_w(const float* __restrict__ W, int k0, int j0, float* v) {
#pragma unroll
    for (int i = 0; i < 24; i++) {
        int idx = i * NTHR + threadIdx.x;   // 0..3071
        int k = idx / 48, c = idx - k * 48;
        int col = ((c >> 4) << 10) + j0 + (c & 15);   // gate*1024 + j
        v[i] = W[(size_t)(k0 + k) * 3072 + col];
    }
}
__device__ __forceinline__ void sts_w(float2* wb, const float* v) {
#pragma unroll
    for (int i = 0; i < 24; i++) {
        int idx = i * NTHR + threadIdx.x;
        int k = idx / 48, c = idx - k * 48;
        wb[k * 48 + c] = make_float2(v[i], v[i]);  // duplicate for f32x2
    }
}

// per-chunk compute: thread = (rg row-group of 8 rows as 4 pairs, cg = one j)
__device__ __forceinline__ void compute_chunk(const float* as, const float2* ws,
                                              int cg, int rg,
                                              ull* az, ull* ar, ull* ah) {
    const ull* ap = (const ull*)(as) + rg * 4;  // rg*8 floats
    const ull* wp = (const ull*)(ws) + cg;
#pragma unroll 4
    for (int k = 0; k < KC; k++) {
        ull wz = wp[k * 48];
        ull wr = wp[k * 48 + 16];
        ull wh = wp[k * 48 + 32];
        const ull* ak = ap + k * 32;            // 64 floats/row-of-k = 32 ull
        ull a0 = ak[0], a1 = ak[1], a2 = ak[2], a3 = ak[3];
        az[0] = fma2(a0, wz, az[0]); ar[0] = fma2(a0, wr, ar[0]); ah[0] = fma2(a0, wh, ah[0]);
        az[1] = fma2(a1, wz, az[1]); ar[1] = fma2(a1, wr, ar[1]); ah[1] = fma2(a1, wh, ah[1]);
        az[2] = fma2(a2, wz, az[2]); ar[2] = fma2(a2, wr, ar[2]); ah[2] = fma2(a2, wh, ah[2]);
        az[3] = fma2(a3, wz, az[3]); ar[3] = fma2(a3, wr, ar[3]); ah[3] = fma2(a3, wh, ah[3]);
    }
}

// double-buffered chunked GEMM accumulation over nch chunks of KC
__device__ __forceinline__ void gemm_phase(const float* abase, const float* __restrict__ W,
                                           int j0, int nch,
                                           float* as0, float* as1, float2* ws0, float2* ws1,
                                           int cg, int rg, ull* az, ull* ar, ull* ah) {
    float v[24];
    ldg_w(W, 0, j0, v);
    sts_w(ws0, v);
    load_a(as0, abase);
    for (int c = 0; c < nch; c++) {
        float*  ac = (c & 1) ? as1 : as0;
        float2* wc = (c & 1) ? ws1 : ws0;
        if (c + 1 < nch) {
            float* an = (c & 1) ? as0 : as1;
            load_a(an, abase + (size_t)(c + 1) * KC * BB);
            ldg_w(W, (c + 1) * KC, j0, v);
            cp_wait1();
        } else {
            cp_wait0();
        }
        __syncthreads();
        compute_chunk(ac, wc, cg, rg, az, ar, ah);
        if (c + 1 < nch) {
            float2* wn = (c & 1) ? ws0 : ws1;
            sts_w(wn, v);
        }
        __syncthreads();
    }
}

// ---------------- persistent recurrent kernel ----------------
__global__ void __launch_bounds__(NTHR, 1)
gru_kernel(const int* __restrict__ enc,
           const float* __restrict__ Wx_f, const float* __restrict__ Wh_f, const float* __restrict__ b_f,
           const float* __restrict__ Wx_b, const float* __restrict__ Wh_b, const float* __restrict__ b_b,
           float* __restrict__ out) {
    extern __shared__ char smem_raw[];
    float*  as0 = (float*)smem_raw;                   // 16 KB
    float*  as1 = as0 + KC * BB;                      // 16 KB
    float2* ws0 = (float2*)(smem_raw + 32 * 1024);    // 24 KB
    float2* ws1 = ws0 + KC * 48;                      // 24 KB

    const int bid = blockIdx.x, tid = threadIdx.x;
    const int d  = bid >> 6;        // direction
    const int p  = bid & 63;        // block within direction
    const int j0 = p << 4;          // 16 j-columns per block
    const int cg = tid & 15;        // j within block
    const int rg = tid >> 4;        // row group (8 rows)
    const int j  = j0 + cg;
    const int r0 = rg << 3;

    const float* Wx   = d ? Wx_b : Wx_f;
    const float* Wh   = d ? Wh_b : Wh_f;
    const float* bias = d ? b_b  : b_f;
    const float bz = bias[j]        + bias[3072 + j];
    const float br = bias[1024 + j] + bias[4096 + j];
    const float bx = bias[2048 + j];
    const float bh = bias[5120 + j];

    float hreg[8], oreg[8];
#pragma unroll
    for (int i = 0; i < 8; i++) { hreg[i] = g_Ht[d][0][j * BB + r0 + i]; oreg[i] = 0.f; }

    ull az[4], ar[4], axh[4], ahh[4];
#pragma unroll
    for (int i = 0; i < 4; i++) { az[i] = 0; ar[i] = 0; axh[i] = 0; ahh[i] = 0; }

    // x-part of step 0 (pipelined x-part accumulates az, ar, axh)
    {
        int t0 = d ? (TT - 1) : 0;
        gemm_phase(g_Xt + (size_t)t0 * EE * BB, Wx, j0, EE / KC,
                   as0, as1, ws0, ws1, cg, rg, az, ar, axh);
    }

    for (int s = 0;; s++) {
        const int t   = d ? (TT - 1 - s) : s;
        const int par = s & 1;

        // recurrent part: hg += h @ Wh
        gemm_phase(g_Ht[d][par], Wh, j0, UU / KC,
                   as0, as1, ws0, ws1, cg, rg, az, ar, ahh);

        // epilogue: gates, masking, writes
        float* hdst = &g_Ht[d][par ^ 1][j * BB + r0];
        const size_t ocol = (size_t)t * 2048 + (size_t)d * UU + j;
#pragma unroll
        for (int i = 0; i < 4; i++) {
            float sz[2] = { lo32(az[i]),  hi32(az[i])  };
            float sr[2] = { lo32(ar[i]),  hi32(ar[i])  };
            float sx[2] = { lo32(axh[i]), hi32(axh[i]) };
            float sh[2] = { lo32(ahh[i]), hi32(ahh[i]) };
#pragma unroll
            for (int l = 0; l < 2; l++) {
                int ridx = 2 * i + l;
                int b = r0 + ridx;
                bool m = (enc[b * TT + t] != 0);
                float ez = __expf(-(sz[l] + bz));
                float z  = __fdividef(1.f, 1.f + ez);
                float er = __expf(-(sr[l] + br));
                float r  = __fdividef(1.f, 1.f + er);
                float hc = tanhf(sx[l] + bx + r * (sh[l] + bh));
                float hn = z * hreg[ridx] + (1.f - z) * hc;
                hn = m ? hn : hreg[ridx];
                float o = m ? hn : oreg[ridx];
                hreg[ridx] = hn;
                oreg[ridx] = o;
                hdst[ridx] = hn;
                out[(size_t)b * (TT * 2048) + ocol] = o;
            }
        }

        if (s == TT - 1) break;

        // arrive: h(s+1) published
        __syncthreads();
        if (tid == 0) { __threadfence(); atomicAdd(&g_count, 1u); }

        // hide barrier latency: x-part of step s+1 (independent of h)
#pragma unroll
        for (int i = 0; i < 4; i++) { az[i] = 0; ar[i] = 0; axh[i] = 0; ahh[i] = 0; }
        {
            int tn = d ? (TT - 2 - s) : (s + 1);
            gemm_phase(g_Xt + (size_t)tn * EE * BB, Wx, j0, EE / KC,
                       as0, as1, ws0, ws1, cg, rg, az, ar, axh);
        }

        // wait: everyone published h(s+1)
        if (tid == 0) {
            unsigned tgt = (unsigned)(s + 1) * NB;
            volatile unsigned* pc = &g_count;
            while (*pc < tgt) { __nanosleep(32); }
            __threadfence();
        }
        __syncthreads();
    }

    // final state: [B, 2U] after the output block
    const size_t STATE_OFF = (size_t)BB * TT * 2048;
#pragma unroll
    for (int i = 0; i < 8; i++) {
        int b = r0 + i;
        out[STATE_OFF + (size_t)b * 2048 + (size_t)d * UU + j] = hreg[i];
    }
}

// ---------------- launcher ----------------
extern "C" void kernel_launch(void* const* d_in, const int* in_sizes, int n_in,
                              void* d_out, int out_size) {
    (void)in_sizes; (void)n_in; (void)out_size;
    const int*   enc = (const int*)  d_in[0];
    const float* h0f = (const float*)d_in[1];
    const float* h0b = (const float*)d_in[2];
    const float* emb = (const float*)d_in[3];
    const float* Wxf = (const float*)d_in[4];
    const float* Whf = (const float*)d_in[5];
    const float* bf  = (const float*)d_in[6];
    const float* Wxb = (const float*)d_in[7];
    const float* Whb = (const float*)d_in[8];
    const float* bb  = (const float*)d_in[9];
    float* out = (float*)d_out;

    // 116 KB dynamic smem: only 80 KB used, padded so at most ONE block fits per SM
    // -> all 128 persistent blocks land on distinct SMs (barrier-safe, no SM sharing).
    const int SMEM_BYTES = 116 * 1024;
    cudaFuncSetAttribute(gru_kernel, cudaFuncAttributeMaxDynamicSharedMemorySize, SMEM_BYTES);

    prep_kernel<<<TT, 256>>>(enc, emb);
    init_kernel<<<512, 256>>>(h0f, h0b);
    gru_kernel<<<NB, NTHR, SMEM_BYTES>>>(enc, Wxf, Whf, bf, Wxb, Whb, bb, out);
}

// round 2
// speedup vs baseline: 1.0448x; 1.0448x over previous
#include <cuda_runtime.h>
#include <cstdint>
#include <cstdio>

// Bidirectional GRU encoder: B=64, T=512, E=512, U=1024, gates (z,r,h), reset_after=True.
// out = [B,T,2U] outputs (fwd|bwd) followed by [B,2U] final state.

#define TT   512   // seq len
#define BB   64    // batch
#define EE   512   // embedding dim
#define UU   1024  // units
#define KC   64    // K-chunk
#define NB   128   // total blocks in persistent kernel (64 per direction)
#define NTHR 256   // threads per block  (2 warps per SMSP -> latency hiding)

typedef unsigned long long ull;

// ---------------- device scratch (static allocation only — no cudaMalloc allowed) ----
__device__ float    g_Xt[(size_t)TT * EE * BB];     // x gathered+transposed: [t][e][b], 64 MB
__device__ float    g_Ht[2][2][UU * BB];            // h state: [dir][parity][u*64+b], 2 MB
__device__ unsigned g_count;                        // global barrier counter

// ---------------- helpers ----------------
__device__ __forceinline__ ull fma2(ull a, ull b, ull c) {
    ull d;
    asm("fma.rn.f32x2 %0, %1, %2, %3;" : "=l"(d) : "l"(a), "l"(b), "l"(c));
    return d;
}
__device__ __forceinline__ ull dup2(float w) {
    // duplicate a float into both halves of a 64-bit pair (for f32x2 broadcast operand)
    ull d;
    asm("mov.b64 %0, {%1, %1};" : "=l"(d) : "f"(w));
    return d;
}
__device__ __forceinline__ float lo32(ull v) { return __uint_as_float((unsigned)v); }
__device__ __forceinline__ float hi32(ull v) { return __uint_as_float((unsigned)(v >> 32)); }

__device__ __forceinline__ void cp16(void* s, const void* g) {
    unsigned sa = (unsigned)__cvta_generic_to_shared(s);
    // .cg: bypass L1.  REQUIRED for g_Ht (cross-SM producer/consumer; L1 is not coherent).
    asm volatile("cp.async.cg.shared.global [%0], [%1], 16;" :: "r"(sa), "l"(g));
}
__device__ __forceinline__ void cp_commit() { asm volatile("cp.async.commit_group;" ::: "memory"); }
__device__ __forceinline__ void cp_wait1()  { asm volatile("cp.async.wait_group 1;" ::: "memory"); }
__device__ __forceinline__ void cp_wait0()  { asm volatile("cp.async.wait_group 0;" ::: "memory"); }

// ---------------- prep: Xt[t][e][b] = emb[enc[b][t]][e] ----------------
__global__ void prep_kernel(const int* __restrict__ enc, const float* __restrict__ emb) {
    int t = blockIdx.x;
    __shared__ int tok[BB];
    if (threadIdx.x < BB) tok[threadIdx.x] = enc[threadIdx.x * TT + t];
    __syncthreads();
    for (int i = threadIdx.x; i < BB * (EE / 4); i += blockDim.x) {
        int b  = i >> 7;
        int e4 = i & 127;
        float4 v = *(const float4*)(emb + (size_t)tok[b] * EE + e4 * 4);
        size_t base = ((size_t)t * EE + (size_t)e4 * 4) * BB + b;
        g_Xt[base]        = v.x;
        g_Xt[base + BB]   = v.y;
        g_Xt[base + 2*BB] = v.z;
        g_Xt[base + 3*BB] = v.w;
    }
}

// ---------------- init: h0 -> g_Ht[dir][0], reset barrier ----------------
__global__ void init_kernel(const float* __restrict__ h0f, const float* __restrict__ h0b) {
    int i = blockIdx.x * blockDim.x + threadIdx.x;  // 0 .. 131071
    if (i == 0) g_count = 0u;
    int d  = i >> 16;
    int r  = i & 65535;
    int jj = r >> 6;
    int b  = r & 63;
    const float* h0 = d ? h0b : h0f;
    g_Ht[d][0][jj * BB + b] = h0[b * UU + jj];
}

// ---------------- GEMM building blocks ----------------
// a-chunk: [KC][64] floats, contiguous 16KB from global
__device__ __forceinline__ void load_a(float* dst, const float* src) {
#pragma unroll
    for (int i = 0; i < 4; i++) {
        int idx = i * NTHR + threadIdx.x;  // float4 index, 1024 total
        cp16(dst + idx * 4, src + idx * 4);
    }
    cp_commit();
}

// w-chunk: 48 columns (3 gates x 16 j) for KC k's.
// SMEM layout: ws[k][cg][4 floats] = {wz, wr, wh, pad} — unduplicated, LDS.128-friendly.
__device__ __forceinline__ void ldg_w(const float* __restrict__ W, int k0, int j0, float* v) {
#pragma unroll
    for (int i = 0; i < 12; i++) {
        int idx  = i * NTHR + threadIdx.x;   // 0..3071
        int k    = idx / 48, c = idx - k * 48;
        int gate = c >> 4;
        int jcg  = c & 15;
        v[i] = W[(size_t)(k0 + k) * 3072 + (gate << 10) + j0 + jcg];
    }
}
__device__ __forceinline__ void sts_w(float* wb, const float* v) {
#pragma unroll
    for (int i = 0; i < 12; i++) {
        int idx  = i * NTHR + threadIdx.x;
        int k    = idx / 48, c = idx - k * 48;
        int gate = c >> 4;
        int jcg  = c & 15;
        wb[k * 64 + jcg * 4 + gate] = v[i];
    }
}

// per-chunk compute: thread = (cg = one j column, rg = row group of 4 rows = 2 pairs)
__device__ __forceinline__ void compute_chunk(const float* as, const float* ws,
                                              int cg, int rg,
                                              ull* az, ull* ar, ull* ah) {
    const ulonglong2* ap = (const ulonglong2*)(as) + rg;        // rg*4 floats (16B units)
    const float4*     wp = (const float4*)(ws) + cg;
#pragma unroll 8
    for (int k = 0; k < KC; k++) {
        float4 w = wp[k * 16];
        ull wz = dup2(w.x), wr = dup2(w.y), wh = dup2(w.z);
        ulonglong2 a = ap[k * 16];                              // one LDS.128 (broadcast)
        az[0] = fma2(a.x, wz, az[0]); ar[0] = fma2(a.x, wr, ar[0]); ah[0] = fma2(a.x, wh, ah[0]);
        az[1] = fma2(a.y, wz, az[1]); ar[1] = fma2(a.y, wr, ar[1]); ah[1] = fma2(a.y, wh, ah[1]);
    }
}

// double-buffered chunked GEMM accumulation over nch chunks of KC
__device__ __forceinline__ void gemm_phase(const float* abase, const float* __restrict__ W,
                                           int j0, int nch,
                                           float* as0, float* as1, float* ws0, float* ws1,
                                           int cg, int rg, ull* az, ull* ar, ull* ah) {
    float v[12];
    ldg_w(W, 0, j0, v);
    sts_w(ws0, v);
    load_a(as0, abase);
    for (int c = 0; c < nch; c++) {
        float* ac = (c & 1) ? as1 : as0;
        float* wc = (c & 1) ? ws1 : ws0;
        if (c + 1 < nch) {
            float* an = (c & 1) ? as0 : as1;
            load_a(an, abase + (size_t)(c + 1) * KC * BB);
            ldg_w(W, (c + 1) * KC, j0, v);
            cp_wait1();
        } else {
            cp_wait0();
        }
        __syncthreads();
        compute_chunk(ac, wc, cg, rg, az, ar, ah);
        if (c + 1 < nch) {
            float* wn = (c & 1) ? ws0 : ws1;
            sts_w(wn, v);
        }
        __syncthreads();
    }
}

// ---------------- persistent recurrent kernel ----------------
__global__ void __launch_bounds__(NTHR, 1)
gru_kernel(const int* __restrict__ enc,
           const float* __restrict__ Wx_f, const float* __restrict__ Wh_f, const float* __restrict__ b_f,
           const float* __restrict__ Wx_b, const float* __restrict__ Wh_b, const float* __restrict__ b_b,
           float* __restrict__ out) {
    extern __shared__ char smem_raw[];
    float* as0 = (float*)smem_raw;                    // 16 KB
    float* as1 = as0 + KC * BB;                       // 16 KB
    float* ws0 = (float*)(smem_raw + 32 * 1024);      // 16 KB  ([KC][16][4] floats)
    float* ws1 = ws0 + KC * 64;                       // 16 KB

    const int bid = blockIdx.x, tid = threadIdx.x;
    const int d  = bid >> 6;        // direction
    const int p  = bid & 63;        // block within direction
    const int j0 = p << 4;          // 16 j-columns per block
    const int cg = tid & 15;        // j within block
    const int rg = tid >> 4;        // row group (4 rows), 0..15
    const int j  = j0 + cg;
    const int r0 = rg << 2;

    const float* Wx   = d ? Wx_b : Wx_f;
    const float* Wh   = d ? Wh_b : Wh_f;
    const float* bias = d ? b_b  : b_f;
    const float bz = bias[j]        + bias[3072 + j];
    const float br = bias[1024 + j] + bias[4096 + j];
    const float bx = bias[2048 + j];
    const float bh = bias[5120 + j];

    float hreg[4], oreg[4];
#pragma unroll
    for (int i = 0; i < 4; i++) { hreg[i] = g_Ht[d][0][j * BB + r0 + i]; oreg[i] = 0.f; }

    ull az[2], ar[2], axh[2], ahh[2];
#pragma unroll
    for (int i = 0; i < 2; i++) { az[i] = 0; ar[i] = 0; axh[i] = 0; ahh[i] = 0; }

    // x-part of step 0 (accumulates az, ar, axh)
    {
        int t0 = d ? (TT - 1) : 0;
        gemm_phase(g_Xt + (size_t)t0 * EE * BB, Wx, j0, EE / KC,
                   as0, as1, ws0, ws1, cg, rg, az, ar, axh);
    }

    for (int s = 0;; s++) {
        const int t   = d ? (TT - 1 - s) : s;
        const int par = s & 1;

        // recurrent part: hg += h @ Wh
        gemm_phase(g_Ht[d][par], Wh, j0, UU / KC,
                   as0, as1, ws0, ws1, cg, rg, az, ar, ahh);

        // epilogue: gates, masking, writes
        float4* hdst = (float4*)&g_Ht[d][par ^ 1][j * BB + r0];
        const size_t ocol = (size_t)t * 2048 + (size_t)d * UU + j;
        float hout[4];
#pragma unroll
        for (int i = 0; i < 2; i++) {
            float sz[2] = { lo32(az[i]),  hi32(az[i])  };
            float sr[2] = { lo32(ar[i]),  hi32(ar[i])  };
            float sx[2] = { lo32(axh[i]), hi32(axh[i]) };
            float sh[2] = { lo32(ahh[i]), hi32(ahh[i]) };
#pragma unroll
            for (int l = 0; l < 2; l++) {
                int ridx = 2 * i + l;
                int b = r0 + ridx;
                bool m = (enc[b * TT + t] != 0);
                float ez = __expf(-(sz[l] + bz));
                float z  = __fdividef(1.f, 1.f + ez);
                float er = __expf(-(sr[l] + br));
                float r  = __fdividef(1.f, 1.f + er);
                float hc = tanhf(sx[l] + bx + r * (sh[l] + bh));
                float hn = z * hreg[ridx] + (1.f - z) * hc;
                hn = m ? hn : hreg[ridx];
                float o = m ? hn : oreg[ridx];
                hreg[ridx] = hn;
                oreg[ridx] = o;
                hout[ridx] = hn;
                out[(size_t)b * (TT * 2048) + ocol] = o;
            }
        }
        *hdst = make_float4(hout[0], hout[1], hout[2], hout[3]);

        if (s == TT - 1) break;

        // arrive: h(s+1) published
        __syncthreads();
        if (tid == 0) { __threadfence(); atomicAdd(&g_count, 1u); }

        // hide barrier latency: x-part of step s+1 (independent of h)
#pragma unroll
        for (int i = 0; i < 2; i++) { az[i] = 0; ar[i] = 0; axh[i] = 0; ahh[i] = 0; }
        {
            int tn = d ? (TT - 2 - s) : (s + 1);
            gemm_phase(g_Xt + (size_t)tn * EE * BB, Wx, j0, EE / KC,
                       as0, as1, ws0, ws1, cg, rg, az, ar, axh);
        }

        // wait: everyone published h(s+1)
        if (tid == 0) {
            unsigned tgt = (unsigned)(s + 1) * NB;
            volatile unsigned* pc = &g_count;
            while (*pc < tgt) { __nanosleep(32); }
            __threadfence();
        }
        __syncthreads();
    }

    // final state: [B, 2U] after the output block
    const size_t STATE_OFF = (size_t)BB * TT * 2048;
#pragma unroll
    for (int i = 0; i < 4; i++) {
        int b = r0 + i;
        out[STATE_OFF + (size_t)b * 2048 + (size_t)d * UU + j] = hreg[i];
    }
}

// ---------------- launcher ----------------
extern "C" void kernel_launch(void* const* d_in, const int* in_sizes, int n_in,
                              void* d_out, int out_size) {
    (void)in_sizes; (void)n_in; (void)out_size;
    const int*   enc = (const int*)  d_in[0];
    const float* h0f = (const float*)d_in[1];
    const float* h0b = (const float*)d_in[2];
    const float* emb = (const float*)d_in[3];
    const float* Wxf = (const float*)d_in[4];
    const float* Whf = (const float*)d_in[5];
    const float* bf  = (const float*)d_in[6];
    const float* Wxb = (const float*)d_in[7];
    const float* Whb = (const float*)d_in[8];
    const float* bb  = (const float*)d_in[9];
    float* out = (float*)d_out;

    // 116 KB dynamic smem: only 64 KB used, padded so at most ONE block fits per SM
    // -> all 128 persistent blocks land on distinct SMs (barrier-safe, no SM sharing).
    const int SMEM_BYTES = 116 * 1024;
    cudaFuncSetAttribute(gru_kernel, cudaFuncAttributeMaxDynamicSharedMemorySize, SMEM_BYTES);

    prep_kernel<<<TT, 256>>>(enc, emb);
    init_kernel<<<512, 256>>>(h0f, h0b);
    gru_kernel<<<NB, NTHR, SMEM_BYTES>>>(enc, Wxf, Whf, bf, Wxb, Whb, bb, out);
}